// round 1
// baseline (speedup 1.0000x reference)
#include <cuda_runtime.h>
#include <cuda_bf16.h>

// Problem dims (fixed)
#define B_DIM 256
#define C_DIM 128
#define I_DIM 512
#define H_DIM 1024
#define O_DIM 128

#define BM 128
#define BN 128
#define BK 16
#define TM 8
#define TN 8
#define NTHREADS 256

// Scratch for hidden activations: [B, C, H] fp32 = 134 MB (static device alloc — allowed)
__device__ float g_H[(size_t)B_DIM * C_DIM * H_DIM];

// -------------------- GEMM1: H[b,c,h] = relu(x[b,c,:] . w1[c,h,:] + b1[c,h]) ------------
// NT gemm per channel c: A = x_c [256 x 512] (row stride C*I), B = w1_c [1024 x 512]
__global__ __launch_bounds__(NTHREADS) void gemm1_kernel(
    const float* __restrict__ x,
    const float* __restrict__ w1,
    const float* __restrict__ b1)
{
    const int c  = blockIdx.z;   // channel
    const int mt = blockIdx.y;   // b-tile (0..1)
    const int nt = blockIdx.x;   // h-tile (0..7)

    __shared__ float As[BK][BM];
    __shared__ float Bs[BK][BN];

    const int tid = threadIdx.x;
    const int tx = tid & 15;     // 0..15 -> n
    const int ty = tid >> 4;     // 0..15 -> m

    // A row m (local) is x[(mt*BM+m)*C + c, :], row stride C_DIM*I_DIM floats
    const float* Abase = x + ((size_t)(mt * BM) * C_DIM + c) * I_DIM;
    const float* Bbase = w1 + ((size_t)c * H_DIM + (size_t)nt * BN) * I_DIM;

    float acc[TM][TN];
    #pragma unroll
    for (int i = 0; i < TM; i++)
        #pragma unroll
        for (int j = 0; j < TN; j++) acc[i][j] = 0.f;

    for (int k0 = 0; k0 < I_DIM; k0 += BK) {
        // Load A tile 128x16, store transposed. 512 float4 loads / 256 threads = 2 each.
        #pragma unroll
        for (int l = 0; l < 2; l++) {
            int f   = tid + l * NTHREADS;        // 0..511
            int row = f >> 2;                    // 0..127
            int kg  = (f & 3) << 2;              // 0,4,8,12
            float4 v = *(const float4*)(Abase + (size_t)row * (C_DIM * I_DIM) + k0 + kg);
            As[kg + 0][row] = v.x; As[kg + 1][row] = v.y;
            As[kg + 2][row] = v.z; As[kg + 3][row] = v.w;
        }
        // Load B tile 128x16, store transposed.
        #pragma unroll
        for (int l = 0; l < 2; l++) {
            int f   = tid + l * NTHREADS;
            int row = f >> 2;
            int kg  = (f & 3) << 2;
            float4 v = *(const float4*)(Bbase + (size_t)row * I_DIM + k0 + kg);
            Bs[kg + 0][row] = v.x; Bs[kg + 1][row] = v.y;
            Bs[kg + 2][row] = v.z; Bs[kg + 3][row] = v.w;
        }
        __syncthreads();

        #pragma unroll
        for (int k = 0; k < BK; k++) {
            float a[TM], b[TN];
            #pragma unroll
            for (int i = 0; i < TM; i++) a[i] = As[k][ty * TM + i];
            #pragma unroll
            for (int j = 0; j < TN; j++) b[j] = Bs[k][tx * TN + j];
            #pragma unroll
            for (int i = 0; i < TM; i++)
                #pragma unroll
                for (int j = 0; j < TN; j++)
                    acc[i][j] = fmaf(a[i], b[j], acc[i][j]);
        }
        __syncthreads();
    }

    // Epilogue: bias + relu, vectorized stores into H scratch
    const float* b1c = b1 + (size_t)c * H_DIM + (size_t)nt * BN;
    #pragma unroll
    for (int i = 0; i < TM; i++) {
        int m    = ty * TM + i;
        int bRow = mt * BM + m;
        float* Hrow = g_H + ((size_t)bRow * C_DIM + c) * H_DIM + (size_t)nt * BN + tx * TN;
        float4 v0, v1;
        v0.x = fmaxf(acc[i][0] + b1c[tx * TN + 0], 0.f);
        v0.y = fmaxf(acc[i][1] + b1c[tx * TN + 1], 0.f);
        v0.z = fmaxf(acc[i][2] + b1c[tx * TN + 2], 0.f);
        v0.w = fmaxf(acc[i][3] + b1c[tx * TN + 3], 0.f);
        v1.x = fmaxf(acc[i][4] + b1c[tx * TN + 4], 0.f);
        v1.y = fmaxf(acc[i][5] + b1c[tx * TN + 5], 0.f);
        v1.z = fmaxf(acc[i][6] + b1c[tx * TN + 6], 0.f);
        v1.w = fmaxf(acc[i][7] + b1c[tx * TN + 7], 0.f);
        *(float4*)(Hrow)     = v0;
        *(float4*)(Hrow + 4) = v1;
    }
}

// -------------------- GEMM2: out[b,o,c] = H[b,c,:] . w2[c,o,:] + b2[c,o] ------------
// NT gemm per channel c: A = H_c [256 x 1024] (row stride C*H), B = w2_c [128 x 1024]
__global__ __launch_bounds__(NTHREADS) void gemm2_kernel(
    const float* __restrict__ w2,
    const float* __restrict__ b2,
    float* __restrict__ out)
{
    const int c  = blockIdx.z;
    const int mt = blockIdx.y;   // b-tile (0..1)
    // single n-tile covers O=128

    __shared__ float As[BK][BM];
    __shared__ float Bs[BK][BN];

    const int tid = threadIdx.x;
    const int tx = tid & 15;
    const int ty = tid >> 4;

    const float* Abase = g_H + ((size_t)(mt * BM) * C_DIM + c) * H_DIM;
    const float* Bbase = w2 + (size_t)c * O_DIM * H_DIM;

    float acc[TM][TN];
    #pragma unroll
    for (int i = 0; i < TM; i++)
        #pragma unroll
        for (int j = 0; j < TN; j++) acc[i][j] = 0.f;

    for (int k0 = 0; k0 < H_DIM; k0 += BK) {
        #pragma unroll
        for (int l = 0; l < 2; l++) {
            int f   = tid + l * NTHREADS;
            int row = f >> 2;
            int kg  = (f & 3) << 2;
            float4 v = *(const float4*)(Abase + (size_t)row * (C_DIM * H_DIM) + k0 + kg);
            As[kg + 0][row] = v.x; As[kg + 1][row] = v.y;
            As[kg + 2][row] = v.z; As[kg + 3][row] = v.w;
        }
        #pragma unroll
        for (int l = 0; l < 2; l++) {
            int f   = tid + l * NTHREADS;
            int row = f >> 2;
            int kg  = (f & 3) << 2;
            float4 v = *(const float4*)(Bbase + (size_t)row * H_DIM + k0 + kg);
            Bs[kg + 0][row] = v.x; Bs[kg + 1][row] = v.y;
            Bs[kg + 2][row] = v.z; Bs[kg + 3][row] = v.w;
        }
        __syncthreads();

        #pragma unroll
        for (int k = 0; k < BK; k++) {
            float a[TM], b[TN];
            #pragma unroll
            for (int i = 0; i < TM; i++) a[i] = As[k][ty * TM + i];
            #pragma unroll
            for (int j = 0; j < TN; j++) b[j] = Bs[k][tx * TN + j];
            #pragma unroll
            for (int i = 0; i < TM; i++)
                #pragma unroll
                for (int j = 0; j < TN; j++)
                    acc[i][j] = fmaf(a[i], b[j], acc[i][j]);
        }
        __syncthreads();
    }

    // Epilogue: bias, write transposed out[b, o, c] (scattered stride-C stores)
    const float* b2c = b2 + (size_t)c * O_DIM;
    #pragma unroll
    for (int i = 0; i < TM; i++) {
        int m    = ty * TM + i;
        int bRow = mt * BM + m;
        float* orow = out + (size_t)bRow * (O_DIM * C_DIM) + c;
        #pragma unroll
        for (int j = 0; j < TN; j++) {
            int n = tx * TN + j;
            orow[(size_t)n * C_DIM] = acc[i][j] + b2c[n];
        }
    }
}

extern "C" void kernel_launch(void* const* d_in, const int* in_sizes, int n_in,
                              void* d_out, int out_size)
{
    const float* x  = (const float*)d_in[0];
    const float* w1 = (const float*)d_in[1];
    const float* b1 = (const float*)d_in[2];
    const float* w2 = (const float*)d_in[3];
    const float* b2 = (const float*)d_in[4];
    float* out = (float*)d_out;

    dim3 grid1(H_DIM / BN, B_DIM / BM, C_DIM);  // (8, 2, 128)
    gemm1_kernel<<<grid1, NTHREADS>>>(x, w1, b1);

    dim3 grid2(1, B_DIM / BM, C_DIM);           // (1, 2, 128)
    gemm2_kernel<<<grid2, NTHREADS>>>(w2, b2, out);
}

// round 3
// speedup vs baseline: 3.5966x; 3.5966x over previous
#include <cuda_runtime.h>
#include <cstdint>

// Problem dims (fixed)
#define B_DIM 256
#define C_DIM 128
#define I_DIM 512
#define H_DIM 1024
#define O_DIM 128

#define BK 32                       // K elems per stage (128 bytes per row)
#define NSTAGE 3
#define STAGE_BYTES ((128 + 256) * 128)   // A(BM<=256)+B tiles: both kernels use BM+BN=384 rows
#define DYN_SMEM (NSTAGE * STAGE_BYTES)

// Hidden activations scratch, layout [c][b][h] (k-contiguous rows for GEMM2)
__device__ float g_H[(size_t)C_DIM * B_DIM * H_DIM];

// ---------------- PTX helpers ----------------
__device__ __forceinline__ void cp16(uint32_t s, const float* g) {
    asm volatile("cp.async.cg.shared.global [%0], [%1], 16;"
                 :: "r"(s), "l"(__cvta_generic_to_global(g)) : "memory");
}
#define CP_COMMIT() asm volatile("cp.async.commit_group;" ::: "memory")
template <int N> __device__ __forceinline__ void cp_wait() {
    asm volatile("cp.async.wait_group %0;" :: "n"(N) : "memory");
}

__device__ __forceinline__ void ldsm4(uint32_t r[4], uint32_t a) {
    asm volatile("ldmatrix.sync.aligned.m8n8.x4.shared.b16 {%0,%1,%2,%3}, [%4];"
                 : "=r"(r[0]), "=r"(r[1]), "=r"(r[2]), "=r"(r[3]) : "r"(a));
}
__device__ __forceinline__ uint32_t f2tf(uint32_t x) {
    uint32_t t;
    asm("cvt.rna.tf32.f32 %0, %1;" : "=r"(t) : "f"(__uint_as_float(x)));
    return t;
}
__device__ __forceinline__ void mma8(float c[4], const uint32_t a[4], uint32_t b0, uint32_t b1) {
    asm volatile("mma.sync.aligned.m16n8k8.row.col.f32.tf32.tf32.f32 "
                 "{%0,%1,%2,%3},{%4,%5,%6,%7},{%8,%9},{%0,%1,%2,%3};"
                 : "+f"(c[0]), "+f"(c[1]), "+f"(c[2]), "+f"(c[3])
                 : "r"(a[0]), "r"(a[1]), "r"(a[2]), "r"(a[3]), "r"(b0), "r"(b1));
}

// ---------------- pipelined tf32 mainloop ----------------
// CTA tile BM x BN, warp grid WGM x WGN of 64x64 warp tiles, 256 threads.
// A: BM rows x 32 k (row-major, k contiguous), B: BN rows x 32 k. NT layout.
// Smem rows are 128B with 16B-chunk XOR swizzle: chunk' = chunk ^ (row & 7).
template <int BM, int BN, int NITER, int WGM, int WGN>
__device__ __forceinline__ void run_mainloop(
    const float* __restrict__ gA, size_t lda,
    const float* __restrict__ gB, size_t ldb,
    uint32_t sb, int tid, float acc[4][8][4])
{
    constexpr int AJ = BM * 8 / 256;   // A cp.async per thread per stage
    constexpr int BJ = BN * 8 / 256;

    const int warpid = tid >> 5, lane = tid & 31;
    const int wm = warpid % WGM, wn = warpid / WGM;

    // ldmatrix per-lane row assignments (see fragment layouts of m16n8k8 tf32)
    const int rowA = wm * 64 + (lane & 7) + ((lane >> 3) & 1) * 8;
    const int a_hi = (lane >> 4) & 1;                // k-chunk select for a2/a3
    const int rowB = wn * 64 + (lane & 7) + ((lane >> 4) & 1) * 8;
    const int b_hi = (lane >> 3) & 1;                // k-chunk select for b1
    const uint32_t baseA = (uint32_t)rowA * 128, swA = rowA & 7;
    const uint32_t baseB = (uint32_t)rowB * 128, swB = rowB & 7;

    auto load_stage = [&](int ki, int slot) {
        uint32_t S  = sb + slot * STAGE_BYTES;
        uint32_t Bs = S + BM * 128;
        const float* ga = gA + (size_t)ki * BK;
        const float* gb = gB + (size_t)ki * BK;
        #pragma unroll
        for (int j = 0; j < AJ; j++) {
            int id = tid + j * 256, row = id >> 3, ch = id & 7;
            cp16(S + row * 128 + ((ch ^ (row & 7)) << 4), ga + (size_t)row * lda + ch * 4);
        }
        #pragma unroll
        for (int j = 0; j < BJ; j++) {
            int id = tid + j * 256, row = id >> 3, ch = id & 7;
            cp16(Bs + row * 128 + ((ch ^ (row & 7)) << 4), gb + (size_t)row * ldb + ch * 4);
        }
        CP_COMMIT();
    };

    load_stage(0, 0);
    load_stage(1, 1);

    #pragma unroll 1
    for (int i = 0; i < NITER; i++) {
        if (i + 1 < NITER) cp_wait<1>(); else cp_wait<0>();
        __syncthreads();
        if (i + 2 < NITER) load_stage(i + 2, (i + 2) % NSTAGE);

        uint32_t S   = sb + (i % NSTAGE) * STAGE_BYTES;
        uint32_t Asm = S, Bsm = S + BM * 128;

        #pragma unroll
        for (int ks = 0; ks < 4; ks++) {           // 4 x k8 per 32-k stage
            uint32_t af[4][4], bf[4][4];
            #pragma unroll
            for (int mi = 0; mi < 4; mi++)
                ldsm4(af[mi], Asm + baseA + mi * 2048 + ((((uint32_t)(ks * 2 + a_hi)) ^ swA) << 4));
            #pragma unroll
            for (int gi = 0; gi < 4; gi++)
                ldsm4(bf[gi], Bsm + baseB + gi * 2048 + ((((uint32_t)(ks * 2 + b_hi)) ^ swB) << 4));
            #pragma unroll
            for (int mi = 0; mi < 4; mi++)
                #pragma unroll
                for (int q = 0; q < 4; q++) af[mi][q] = f2tf(af[mi][q]);
            #pragma unroll
            for (int gi = 0; gi < 4; gi++)
                #pragma unroll
                for (int q = 0; q < 4; q++) bf[gi][q] = f2tf(bf[gi][q]);
            #pragma unroll
            for (int mi = 0; mi < 4; mi++)
                #pragma unroll
                for (int gi = 0; gi < 4; gi++) {
                    mma8(acc[mi][2 * gi],     af[mi], bf[gi][0], bf[gi][1]);
                    mma8(acc[mi][2 * gi + 1], af[mi], bf[gi][2], bf[gi][3]);
                }
        }
    }
}

// ---------------- GEMM1: g_H[c][b][h] = relu(x[b,c,:] . w1[c,h,:] + b1[c,h]) ----------------
// A = x_c (M=128 b-rows per CTA), B = w1_c (N=256 h-rows per CTA)
__global__ void __launch_bounds__(256, 1) gemm1_mma(
    const float* __restrict__ x, const float* __restrict__ w1, const float* __restrict__ b1)
{
    extern __shared__ char smem[];
    uint32_t sb = (uint32_t)__cvta_generic_to_shared(smem);
    const int tid = threadIdx.x;
    const int mt = blockIdx.x, nt = blockIdx.y, c = blockIdx.z;

    const float* gA = x  + ((size_t)(mt * 128) * C_DIM + c) * I_DIM;   // row stride C*I
    const float* gB = w1 + ((size_t)c * H_DIM + nt * 256) * I_DIM;     // row stride I

    float acc[4][8][4] = {};
    run_mainloop<128, 256, I_DIM / BK, 2, 4>(gA, (size_t)C_DIM * I_DIM, gB, I_DIM, sb, tid, acc);

    const int warpid = tid >> 5, lane = tid & 31;
    const int wm = warpid & 1, wn = warpid >> 1;
    const int m0 = mt * 128 + wm * 64;
    const int n0 = nt * 256 + wn * 64;
    const float* b1c = b1 + (size_t)c * H_DIM;

    #pragma unroll
    for (int mi = 0; mi < 4; mi++) {
        int r0 = m0 + mi * 16 + (lane >> 2);
        float* h0 = g_H + ((size_t)c * B_DIM + r0) * H_DIM;
        float* h1 = h0 + 8 * H_DIM;
        #pragma unroll
        for (int nj = 0; nj < 8; nj++) {
            int col = n0 + nj * 8 + 2 * (lane & 3);
            float bi0 = b1c[col], bi1 = b1c[col + 1];
            float2 v0, v1;
            v0.x = fmaxf(acc[mi][nj][0] + bi0, 0.f);
            v0.y = fmaxf(acc[mi][nj][1] + bi1, 0.f);
            v1.x = fmaxf(acc[mi][nj][2] + bi0, 0.f);
            v1.y = fmaxf(acc[mi][nj][3] + bi1, 0.f);
            *(float2*)(h0 + col) = v0;
            *(float2*)(h1 + col) = v1;
        }
    }
}

// ---------------- GEMM2: out[b][o][c] = g_H[c][b][:] . w2[c,o,:] + b2[c,o] ----------------
// A = g_H_c (M=256 b-rows), B = w2_c (N=128 o-rows); one CTA per channel.
__global__ void __launch_bounds__(256, 1) gemm2_mma(
    const float* __restrict__ w2, const float* __restrict__ b2, float* __restrict__ out)
{
    extern __shared__ char smem[];
    uint32_t sb = (uint32_t)__cvta_generic_to_shared(smem);
    const int tid = threadIdx.x;
    const int c = blockIdx.x;

    const float* gA = g_H + (size_t)c * B_DIM * H_DIM;   // row stride H
    const float* gB = w2  + (size_t)c * O_DIM * H_DIM;   // row stride H

    float acc[4][8][4] = {};
    run_mainloop<256, 128, H_DIM / BK, 4, 2>(gA, H_DIM, gB, H_DIM, sb, tid, acc);

    const int warpid = tid >> 5, lane = tid & 31;
    const int wm = warpid & 3, wn = warpid >> 2;
    const int m0 = wm * 64, n0 = wn * 64;
    const float* b2c = b2 + (size_t)c * O_DIM;

    #pragma unroll
    for (int mi = 0; mi < 4; mi++) {
        int r0 = m0 + mi * 16 + (lane >> 2);
        float* o0 = out + (size_t)r0 * (O_DIM * C_DIM) + c;
        float* o1 = o0 + (size_t)8 * (O_DIM * C_DIM);
        #pragma unroll
        for (int nj = 0; nj < 8; nj++) {
            int o = n0 + nj * 8 + 2 * (lane & 3);
            float bi0 = b2c[o], bi1 = b2c[o + 1];
            o0[(size_t)o * C_DIM]        = acc[mi][nj][0] + bi0;
            o0[(size_t)(o + 1) * C_DIM]  = acc[mi][nj][1] + bi1;
            o1[(size_t)o * C_DIM]        = acc[mi][nj][2] + bi0;
            o1[(size_t)(o + 1) * C_DIM]  = acc[mi][nj][3] + bi1;
        }
    }
}

extern "C" void kernel_launch(void* const* d_in, const int* in_sizes, int n_in,
                              void* d_out, int out_size)
{
    const float* x  = (const float*)d_in[0];
    const float* w1 = (const float*)d_in[1];
    const float* b1 = (const float*)d_in[2];
    const float* w2 = (const float*)d_in[3];
    const float* b2 = (const float*)d_in[4];
    float* out = (float*)d_out;

    cudaFuncSetAttribute(gemm1_mma, cudaFuncAttributeMaxDynamicSharedMemorySize, DYN_SMEM);
    cudaFuncSetAttribute(gemm2_mma, cudaFuncAttributeMaxDynamicSharedMemorySize, DYN_SMEM);

    // x-fastest launch order: the 2 mt CTAs sharing a w1 tile are adjacent,
    // and all 8 CTAs of one channel are co-resident (L2 reuse of x and w1).
    dim3 g1(B_DIM / 128, H_DIM / 256, C_DIM);   // (2, 4, 128)
    gemm1_mma<<<g1, 256, DYN_SMEM>>>(x, w1, b1);
    gemm2_mma<<<C_DIM, 256, DYN_SMEM>>>(w2, b2, out);
}

// round 4
// speedup vs baseline: 3.6416x; 1.0125x over previous
#include <cuda_runtime.h>
#include <cstdint>

// Problem dims (fixed)
#define B_DIM 256
#define C_DIM 128
#define I_DIM 512
#define H_DIM 1024
#define O_DIM 128

#define BK 32                       // K elems per stage (128 bytes per row)
#define NSTAGE 4
#define STAGE_BYTES ((128 + 256) * 128)   // A+B tiles: both kernels use BM+BN=384 rows
#define DYN_SMEM (NSTAGE * STAGE_BYTES)   // 196608

// Hidden activations scratch, layout [c][b][h] (k-contiguous rows for GEMM2)
__device__ float g_H[(size_t)C_DIM * B_DIM * H_DIM];

// ---------------- PTX helpers ----------------
__device__ __forceinline__ void cp16(uint32_t s, const float* g) {
    asm volatile("cp.async.cg.shared.global [%0], [%1], 16;"
                 :: "r"(s), "l"(__cvta_generic_to_global(g)) : "memory");
}
#define CP_COMMIT() asm volatile("cp.async.commit_group;" ::: "memory")
template <int N> __device__ __forceinline__ void cp_wait() {
    asm volatile("cp.async.wait_group %0;" :: "n"(N) : "memory");
}

__device__ __forceinline__ void ldsm4(uint32_t r[4], uint32_t a) {
    asm volatile("ldmatrix.sync.aligned.m8n8.x4.shared.b16 {%0,%1,%2,%3}, [%4];"
                 : "=r"(r[0]), "=r"(r[1]), "=r"(r[2]), "=r"(r[3]) : "r"(a));
}
__device__ __forceinline__ uint32_t f2tf(uint32_t x) {
    uint32_t t;
    asm("cvt.rna.tf32.f32 %0, %1;" : "=r"(t) : "f"(__uint_as_float(x)));
    return t;
}
__device__ __forceinline__ void mma8(float c[4], const uint32_t a[4], uint32_t b0, uint32_t b1) {
    asm volatile("mma.sync.aligned.m16n8k8.row.col.f32.tf32.tf32.f32 "
                 "{%0,%1,%2,%3},{%4,%5,%6,%7},{%8,%9},{%0,%1,%2,%3};"
                 : "+f"(c[0]), "+f"(c[1]), "+f"(c[2]), "+f"(c[3])
                 : "r"(a[0]), "r"(a[1]), "r"(a[2]), "r"(a[3]), "r"(b0), "r"(b1));
}

// ---------------- pipelined tf32 mainloop ----------------
// CTA tile BM x BN, warp grid WGM x WGN of 64x64 warp tiles, 256 threads.
// A: BM rows x 32 k (k contiguous), B: BN rows x 32 k. NT layout.
// Smem rows 128B, 16B-chunk XOR swizzle: chunk' = chunk ^ (row & 7).
// Fragments double-buffered across k8 steps to hide LDSM latency.
template <int BM, int BN, int NITER, int WGM, int WGN>
__device__ __forceinline__ void run_mainloop(
    const float* __restrict__ gA, size_t lda,
    const float* __restrict__ gB, size_t ldb,
    uint32_t sb, int tid, float acc[4][8][4])
{
    constexpr int AJ = BM * 8 / 256;   // A cp.async per thread per stage
    constexpr int BJ = BN * 8 / 256;

    const int warpid = tid >> 5, lane = tid & 31;
    const int wm = warpid % WGM, wn = warpid / WGM;

    // ldmatrix per-lane row assignments (m16n8k8 tf32 fragment layouts)
    const int rowA = wm * 64 + (lane & 7) + ((lane >> 3) & 1) * 8;
    const int a_hi = (lane >> 4) & 1;                // k-chunk select for a2/a3
    const int rowB = wn * 64 + (lane & 7) + ((lane >> 4) & 1) * 8;
    const int b_hi = (lane >> 3) & 1;                // k-chunk select for b1
    const uint32_t baseA = (uint32_t)rowA * 128, swA = rowA & 7;
    const uint32_t baseB = (uint32_t)rowB * 128, swB = rowB & 7;

    auto load_stage = [&](int ki, int slot) {
        uint32_t S  = sb + slot * STAGE_BYTES;
        uint32_t Bs = S + BM * 128;
        const float* ga = gA + (size_t)ki * BK;
        const float* gb = gB + (size_t)ki * BK;
        #pragma unroll
        for (int j = 0; j < AJ; j++) {
            int id = tid + j * 256, row = id >> 3, ch = id & 7;
            cp16(S + row * 128 + ((ch ^ (row & 7)) << 4), ga + (size_t)row * lda + ch * 4);
        }
        #pragma unroll
        for (int j = 0; j < BJ; j++) {
            int id = tid + j * 256, row = id >> 3, ch = id & 7;
            cp16(Bs + row * 128 + ((ch ^ (row & 7)) << 4), gb + (size_t)row * ldb + ch * 4);
        }
        CP_COMMIT();
    };

    load_stage(0, 0);
    load_stage(1, 1);
    load_stage(2, 2);

    uint32_t af[2][4][4], bf[2][4][4];

    #pragma unroll 1
    for (int i = 0; i < NITER; i++) {
        if (i + 3 <= NITER)      cp_wait<2>();
        else if (i + 2 == NITER) cp_wait<1>();
        else                     cp_wait<0>();
        __syncthreads();
        if (i + 3 < NITER) load_stage(i + 3, (i + 3) % NSTAGE);

        uint32_t S   = sb + (i % NSTAGE) * STAGE_BYTES;
        uint32_t Asm = S, Bsm = S + BM * 128;

        auto load_frags = [&](int ks, int buf) {
            #pragma unroll
            for (int mi = 0; mi < 4; mi++)
                ldsm4(af[buf][mi], Asm + baseA + mi * 2048 + ((((uint32_t)(ks * 2 + a_hi)) ^ swA) << 4));
            #pragma unroll
            for (int gi = 0; gi < 4; gi++)
                ldsm4(bf[buf][gi], Bsm + baseB + gi * 2048 + ((((uint32_t)(ks * 2 + b_hi)) ^ swB) << 4));
        };

        load_frags(0, 0);

        #pragma unroll
        for (int ks = 0; ks < 4; ks++) {           // 4 x k8 per 32-k stage
            int cur = ks & 1;
            if (ks < 3) load_frags(ks + 1, cur ^ 1);   // prefetch next k8 fragments
            #pragma unroll
            for (int mi = 0; mi < 4; mi++)
                #pragma unroll
                for (int q = 0; q < 4; q++) af[cur][mi][q] = f2tf(af[cur][mi][q]);
            #pragma unroll
            for (int gi = 0; gi < 4; gi++)
                #pragma unroll
                for (int q = 0; q < 4; q++) bf[cur][gi][q] = f2tf(bf[cur][gi][q]);
            #pragma unroll
            for (int mi = 0; mi < 4; mi++)
                #pragma unroll
                for (int gi = 0; gi < 4; gi++) {
                    mma8(acc[mi][2 * gi],     af[cur][mi], bf[cur][gi][0], bf[cur][gi][1]);
                    mma8(acc[mi][2 * gi + 1], af[cur][mi], bf[cur][gi][2], bf[cur][gi][3]);
                }
        }
    }
}

// ---------------- GEMM1: g_H[c][b][h] = relu(x[b,c,:] . w1[c,h,:] + b1[c,h]) ----------------
// A = x_c (M=128 b-rows per CTA), B = w1_c (N=256 h-rows per CTA)
__global__ void __launch_bounds__(256, 1) gemm1_mma(
    const float* __restrict__ x, const float* __restrict__ w1, const float* __restrict__ b1)
{
    extern __shared__ char smem[];
    uint32_t sb = (uint32_t)__cvta_generic_to_shared(smem);
    const int tid = threadIdx.x;
    const int mt = blockIdx.x, nt = blockIdx.y, c = blockIdx.z;

    const float* gA = x  + ((size_t)(mt * 128) * C_DIM + c) * I_DIM;   // row stride C*I
    const float* gB = w1 + ((size_t)c * H_DIM + nt * 256) * I_DIM;     // row stride I

    float acc[4][8][4] = {};
    run_mainloop<128, 256, I_DIM / BK, 2, 4>(gA, (size_t)C_DIM * I_DIM, gB, I_DIM, sb, tid, acc);

    const int warpid = tid >> 5, lane = tid & 31;
    const int wm = warpid & 1, wn = warpid >> 1;
    const int m0 = mt * 128 + wm * 64;
    const int n0 = nt * 256 + wn * 64;
    const float* b1c = b1 + (size_t)c * H_DIM;

    #pragma unroll
    for (int mi = 0; mi < 4; mi++) {
        int r0 = m0 + mi * 16 + (lane >> 2);
        float* h0 = g_H + ((size_t)c * B_DIM + r0) * H_DIM;
        float* h1 = h0 + 8 * H_DIM;
        #pragma unroll
        for (int nj = 0; nj < 8; nj++) {
            int col = n0 + nj * 8 + 2 * (lane & 3);
            float bi0 = b1c[col], bi1 = b1c[col + 1];
            float2 v0, v1;
            v0.x = fmaxf(acc[mi][nj][0] + bi0, 0.f);
            v0.y = fmaxf(acc[mi][nj][1] + bi1, 0.f);
            v1.x = fmaxf(acc[mi][nj][2] + bi0, 0.f);
            v1.y = fmaxf(acc[mi][nj][3] + bi1, 0.f);
            *(float2*)(h0 + col) = v0;
            *(float2*)(h1 + col) = v1;
        }
    }
}

// ---------------- GEMM2: out[b][o][c] = g_H[c][b][:] . w2[c,o,:] + b2[c,o] ----------------
// A = g_H_c (M=256 b-rows), B = w2_c (N=128 o-rows); one CTA per channel.
__global__ void __launch_bounds__(256, 1) gemm2_mma(
    const float* __restrict__ w2, const float* __restrict__ b2, float* __restrict__ out)
{
    extern __shared__ char smem[];
    uint32_t sb = (uint32_t)__cvta_generic_to_shared(smem);
    const int tid = threadIdx.x;
    const int c = blockIdx.x;

    const float* gA = g_H + (size_t)c * B_DIM * H_DIM;   // row stride H
    const float* gB = w2  + (size_t)c * O_DIM * H_DIM;   // row stride H

    float acc[4][8][4] = {};
    run_mainloop<256, 128, H_DIM / BK, 4, 2>(gA, H_DIM, gB, H_DIM, sb, tid, acc);

    const int warpid = tid >> 5, lane = tid & 31;
    const int wm = warpid & 3, wn = warpid >> 2;
    const int m0 = wm * 64, n0 = wn * 64;
    const float* b2c = b2 + (size_t)c * O_DIM;

    #pragma unroll
    for (int mi = 0; mi < 4; mi++) {
        int r0 = m0 + mi * 16 + (lane >> 2);
        float* o0 = out + (size_t)r0 * (O_DIM * C_DIM) + c;
        float* o1 = o0 + (size_t)8 * (O_DIM * C_DIM);
        #pragma unroll
        for (int nj = 0; nj < 8; nj++) {
            int o = n0 + nj * 8 + 2 * (lane & 3);
            float bi0 = b2c[o], bi1 = b2c[o + 1];
            o0[(size_t)o * C_DIM]        = acc[mi][nj][0] + bi0;
            o0[(size_t)(o + 1) * C_DIM]  = acc[mi][nj][1] + bi1;
            o1[(size_t)o * C_DIM]        = acc[mi][nj][2] + bi0;
            o1[(size_t)(o + 1) * C_DIM]  = acc[mi][nj][3] + bi1;
        }
    }
}

extern "C" void kernel_launch(void* const* d_in, const int* in_sizes, int n_in,
                              void* d_out, int out_size)
{
    const float* x  = (const float*)d_in[0];
    const float* w1 = (const float*)d_in[1];
    const float* b1 = (const float*)d_in[2];
    const float* w2 = (const float*)d_in[3];
    const float* b2 = (const float*)d_in[4];
    float* out = (float*)d_out;

    cudaFuncSetAttribute(gemm1_mma, cudaFuncAttributeMaxDynamicSharedMemorySize, DYN_SMEM);
    cudaFuncSetAttribute(gemm2_mma, cudaFuncAttributeMaxDynamicSharedMemorySize, DYN_SMEM);

    // x-fastest launch order: the 2 mt CTAs sharing a w1 tile are adjacent,
    // and all 8 CTAs of one channel are co-resident (L2 reuse of x and w1).
    dim3 g1(B_DIM / 128, H_DIM / 256, C_DIM);   // (2, 4, 128)
    gemm1_mma<<<g1, 256, DYN_SMEM>>>(x, w1, b1);
    gemm2_mma<<<C_DIM, 256, DYN_SMEM>>>(w2, b2, out);
}

// round 6
// speedup vs baseline: 3.6722x; 1.0084x over previous
#include <cuda_runtime.h>
#include <cstdint>

// Problem dims (fixed)
#define B_DIM 256
#define C_DIM 128
#define I_DIM 512
#define H_DIM 1024
#define O_DIM 128

#define BK 32                              // K elems per stage (128B rows)
#define NSTAGE 3
#define STAGE_BYTES ((128 + 128) * 128)    // A(128 rows)+B(128 rows) = 32KB
#define DYN_SMEM (NSTAGE * STAGE_BYTES)    // 98304 -> 2 CTAs/SM

// Hidden activations scratch, layout [c][b][h] (k-contiguous rows for GEMM2)
__device__ float g_H[(size_t)C_DIM * B_DIM * H_DIM];

// ---------------- PTX helpers ----------------
__device__ __forceinline__ void cp16(uint32_t s, const float* g) {
    asm volatile("cp.async.cg.shared.global [%0], [%1], 16;"
                 :: "r"(s), "l"(__cvta_generic_to_global(g)) : "memory");
}
#define CP_COMMIT() asm volatile("cp.async.commit_group;" ::: "memory")
template <int N> __device__ __forceinline__ void cp_wait() {
    asm volatile("cp.async.wait_group %0;" :: "n"(N) : "memory");
}
__device__ __forceinline__ void ldsm4(uint32_t r[4], uint32_t a) {
    asm volatile("ldmatrix.sync.aligned.m8n8.x4.shared.b16 {%0,%1,%2,%3}, [%4];"
                 : "=r"(r[0]), "=r"(r[1]), "=r"(r[2]), "=r"(r[3]) : "r"(a));
}
__device__ __forceinline__ uint32_t f2tf(uint32_t x) {
    uint32_t t;
    asm("cvt.rna.tf32.f32 %0, %1;" : "=r"(t) : "f"(__uint_as_float(x)));
    return t;
}
__device__ __forceinline__ void mma8(float c[4], const uint32_t a[4], uint32_t b0, uint32_t b1) {
    asm volatile("mma.sync.aligned.m16n8k8.row.col.f32.tf32.tf32.f32 "
                 "{%0,%1,%2,%3},{%4,%5,%6,%7},{%8,%9},{%0,%1,%2,%3};"
                 : "+f"(c[0]), "+f"(c[1]), "+f"(c[2]), "+f"(c[3])
                 : "r"(a[0]), "r"(a[1]), "r"(a[2]), "r"(a[3]), "r"(b0), "r"(b1));
}

// ---------------- pipelined tf32 mainloop ----------------
// CTA tile 128x128, 8 warps in 2(M) x 4(N) grid of 64x32 warp tiles.
// A: 128 rows x 32 k (k contiguous), B: 128 rows x 32 k. NT layout.
// Smem rows 128B, 16B-chunk XOR swizzle: chunk' = chunk ^ (row & 7).
template <int NITER>
__device__ __forceinline__ void run_mainloop(
    const float* __restrict__ gA, size_t lda,
    const float* __restrict__ gB, size_t ldb,
    uint32_t sb, int tid, float acc[4][4][4])
{
    const int warpid = tid >> 5, lane = tid & 31;
    const int wm = warpid & 1, wn = warpid >> 1;

    // ldmatrix per-lane row assignments (m16n8k8 tf32 fragment layouts)
    const int rowA = wm * 64 + (lane & 7) + ((lane >> 3) & 1) * 8;
    const int a_hi = (lane >> 4) & 1;                // k-chunk select for a2/a3
    const int rowB = wn * 32 + (lane & 7) + ((lane >> 4) & 1) * 8;
    const int b_hi = (lane >> 3) & 1;                // k-chunk select for b1
    const uint32_t baseA = (uint32_t)rowA * 128, swA = rowA & 7;
    const uint32_t baseB = (uint32_t)rowB * 128, swB = rowB & 7;

    auto load_stage = [&](int ki, int slot) {
        uint32_t S  = sb + slot * STAGE_BYTES;
        uint32_t Bs = S + 128 * 128;
        const float* ga = gA + (size_t)ki * BK;
        const float* gb = gB + (size_t)ki * BK;
        #pragma unroll
        for (int j = 0; j < 4; j++) {   // A: 128 rows x 8 chunks = 1024 / 256 thr
            int id = tid + j * 256, row = id >> 3, ch = id & 7;
            cp16(S + row * 128 + ((ch ^ (row & 7)) << 4), ga + (size_t)row * lda + ch * 4);
        }
        #pragma unroll
        for (int j = 0; j < 4; j++) {   // B: 128 rows x 8 chunks
            int id = tid + j * 256, row = id >> 3, ch = id & 7;
            cp16(Bs + row * 128 + ((ch ^ (row & 7)) << 4), gb + (size_t)row * ldb + ch * 4);
        }
        CP_COMMIT();
    };

    load_stage(0, 0);
    load_stage(1, 1);

    #pragma unroll 1
    for (int i = 0; i < NITER; i++) {
        if (i + 1 < NITER) cp_wait<1>(); else cp_wait<0>();
        __syncthreads();
        if (i + 2 < NITER) load_stage(i + 2, (i + 2) % NSTAGE);

        uint32_t S   = sb + (i % NSTAGE) * STAGE_BYTES;
        uint32_t Asm = S, Bsm = S + 128 * 128;

        #pragma unroll
        for (int ks = 0; ks < 4; ks++) {           // 4 x k8 per 32-k stage
            uint32_t af[4][4], bf[2][4];
            #pragma unroll
            for (int mi = 0; mi < 4; mi++)
                ldsm4(af[mi], Asm + baseA + mi * 2048 + ((((uint32_t)(ks * 2 + a_hi)) ^ swA) << 4));
            #pragma unroll
            for (int gi = 0; gi < 2; gi++)
                ldsm4(bf[gi], Bsm + baseB + gi * 2048 + ((((uint32_t)(ks * 2 + b_hi)) ^ swB) << 4));
            #pragma unroll
            for (int mi = 0; mi < 4; mi++)
                #pragma unroll
                for (int q = 0; q < 4; q++) af[mi][q] = f2tf(af[mi][q]);
            #pragma unroll
            for (int gi = 0; gi < 2; gi++)
                #pragma unroll
                for (int q = 0; q < 4; q++) bf[gi][q] = f2tf(bf[gi][q]);
            #pragma unroll
            for (int mi = 0; mi < 4; mi++)
                #pragma unroll
                for (int gi = 0; gi < 2; gi++) {
                    mma8(acc[mi][2 * gi],     af[mi], bf[gi][0], bf[gi][1]);
                    mma8(acc[mi][2 * gi + 1], af[mi], bf[gi][2], bf[gi][3]);
                }
        }
    }
}

// ---------------- GEMM1: g_H[c][b][h] = relu(x[b,c,:] . w1[c,h,:] + b1[c,h]) ----------------
// A = x_c (M=128 b-rows per CTA), B = w1_c (N=128 h-rows per CTA)
__global__ void __launch_bounds__(256, 2) gemm1_mma(
    const float* __restrict__ x, const float* __restrict__ w1, const float* __restrict__ b1)
{
    extern __shared__ char smem[];
    uint32_t sb = (uint32_t)__cvta_generic_to_shared(smem);
    const int tid = threadIdx.x;
    const int nt = blockIdx.x, mt = blockIdx.y, c = blockIdx.z;

    const float* gA = x  + ((size_t)(mt * 128) * C_DIM + c) * I_DIM;   // row stride C*I
    const float* gB = w1 + ((size_t)c * H_DIM + nt * 128) * I_DIM;     // row stride I

    float acc[4][4][4] = {};
    run_mainloop<I_DIM / BK>(gA, (size_t)C_DIM * I_DIM, gB, I_DIM, sb, tid, acc);

    const int warpid = tid >> 5, lane = tid & 31;
    const int wm = warpid & 1, wn = warpid >> 1;
    const int m0 = mt * 128 + wm * 64;
    const int n0 = nt * 128 + wn * 32;
    const float* b1c = b1 + (size_t)c * H_DIM;

    #pragma unroll
    for (int mi = 0; mi < 4; mi++) {
        int r0 = m0 + mi * 16 + (lane >> 2);
        float* h0 = g_H + ((size_t)c * B_DIM + r0) * H_DIM;
        float* h1 = h0 + 8 * H_DIM;
        #pragma unroll
        for (int nj = 0; nj < 4; nj++) {
            int col = n0 + nj * 8 + 2 * (lane & 3);
            float bi0 = b1c[col], bi1 = b1c[col + 1];
            float2 v0, v1;
            v0.x = fmaxf(acc[mi][nj][0] + bi0, 0.f);
            v0.y = fmaxf(acc[mi][nj][1] + bi1, 0.f);
            v1.x = fmaxf(acc[mi][nj][2] + bi0, 0.f);
            v1.y = fmaxf(acc[mi][nj][3] + bi1, 0.f);
            *(float2*)(h0 + col) = v0;
            *(float2*)(h1 + col) = v1;
        }
    }
}

// ---------------- GEMM2: out[b][o][c] = g_H[c][b][:] . w2[c,o,:] + b2[c,o] ----------------
// A = g_H_c (M=128 b-rows per CTA), B = w2_c (N=128 o-rows); 2 CTAs per channel.
__global__ void __launch_bounds__(256, 2) gemm2_mma(
    const float* __restrict__ w2, const float* __restrict__ b2, float* __restrict__ out)
{
    extern __shared__ char smem[];
    uint32_t sb = (uint32_t)__cvta_generic_to_shared(smem);
    const int tid = threadIdx.x;
    const int mt = blockIdx.x, c = blockIdx.y;

    const float* gA = g_H + ((size_t)c * B_DIM + mt * 128) * H_DIM;   // row stride H
    const float* gB = w2  + (size_t)c * O_DIM * H_DIM;                // row stride H

    float acc[4][4][4] = {};
    run_mainloop<H_DIM / BK>(gA, H_DIM, gB, H_DIM, sb, tid, acc);

    const int warpid = tid >> 5, lane = tid & 31;
    const int wm = warpid & 1, wn = warpid >> 1;
    const int m0 = mt * 128 + wm * 64;
    const int n0 = wn * 32;
    const float* b2c = b2 + (size_t)c * O_DIM;

    #pragma unroll
    for (int mi = 0; mi < 4; mi++) {
        int r0 = m0 + mi * 16 + (lane >> 2);
        float* o0 = out + (size_t)r0 * (O_DIM * C_DIM) + c;
        float* o1 = o0 + (size_t)8 * (O_DIM * C_DIM);
        #pragma unroll
        for (int nj = 0; nj < 4; nj++) {
            int o = n0 + nj * 8 + 2 * (lane & 3);
            float bi0 = b2c[o], bi1 = b2c[o + 1];
            o0[(size_t)o * C_DIM]        = acc[mi][nj][0] + bi0;
            o0[(size_t)(o + 1) * C_DIM]  = acc[mi][nj][1] + bi1;
            o1[(size_t)o * C_DIM]        = acc[mi][nj][2] + bi0;
            o1[(size_t)(o + 1) * C_DIM]  = acc[mi][nj][3] + bi1;
        }
    }
}

extern "C" void kernel_launch(void* const* d_in, const int* in_sizes, int n_in,
                              void* d_out, int out_size)
{
    const float* x  = (const float*)d_in[0];
    const float* w1 = (const float*)d_in[1];
    const float* b1 = (const float*)d_in[2];
    const float* w2 = (const float*)d_in[3];
    const float* b2 = (const float*)d_in[4];
    float* out = (float*)d_out;

    cudaFuncSetAttribute(gemm1_mma, cudaFuncAttributeMaxDynamicSharedMemorySize, DYN_SMEM);
    cudaFuncSetAttribute(gemm2_mma, cudaFuncAttributeMaxDynamicSharedMemorySize, DYN_SMEM);

    // x-fastest = nt: the 8 CTAs sharing one x slice (mt,c) are adjacent -> L2 reuse.
    dim3 g1(H_DIM / 128, B_DIM / 128, C_DIM);   // (8, 2, 128) = 2048 CTAs
    gemm1_mma<<<g1, 256, DYN_SMEM>>>(x, w1, b1);

    dim3 g2(B_DIM / 128, C_DIM);                // (2, 128) = 256 CTAs, all resident
    gemm2_mma<<<g2, 256, DYN_SMEM>>>(w2, b2, out);
}

// round 14
// speedup vs baseline: 4.2271x; 1.1511x over previous
#include <cuda_runtime.h>
#include <cstdint>

// Problem dims (fixed)
#define B_DIM 256
#define C_DIM 128
#define I_DIM 512
#define H_DIM 1024
#define O_DIM 128

#define BK 32                              // K elems per stage (128B rows)
#define NSTAGE 3
#define STAGE_BYTES ((128 + 128) * 128)    // A(128 rows)+B(128 rows) = 32KB
#define DYN_SMEM (NSTAGE * STAGE_BYTES)    // 98304 -> 2 CTAs/SM

// Hidden activations scratch, layout [c][b][h]; values stored tf32-rna-rounded.
__device__ float g_H[(size_t)C_DIM * B_DIM * H_DIM];
// gemm2 output staging, layout [c][b][o] (coalesced along o)
__device__ float g_O[(size_t)C_DIM * B_DIM * O_DIM];

// ---------------- PTX helpers ----------------
__device__ __forceinline__ void cp16(uint32_t s, const float* g) {
    asm volatile("cp.async.cg.shared.global [%0], [%1], 16;"
                 :: "r"(s), "l"(__cvta_generic_to_global(g)) : "memory");
}
#define CP_COMMIT() asm volatile("cp.async.commit_group;" ::: "memory")
template <int N> __device__ __forceinline__ void cp_wait() {
    asm volatile("cp.async.wait_group %0;" :: "n"(N) : "memory");
}
__device__ __forceinline__ void ldsm4(uint32_t r[4], uint32_t a) {
    asm volatile("ldmatrix.sync.aligned.m8n8.x4.shared.b16 {%0,%1,%2,%3}, [%4];"
                 : "=r"(r[0]), "=r"(r[1]), "=r"(r[2]), "=r"(r[3]) : "r"(a));
}
__device__ __forceinline__ uint32_t f2tf(uint32_t x) {
    uint32_t t;
    asm("cvt.rna.tf32.f32 %0, %1;" : "=r"(t) : "f"(__uint_as_float(x)));
    return t;
}
__device__ __forceinline__ float f2tf_f(float x) {
    uint32_t t;
    asm("cvt.rna.tf32.f32 %0, %1;" : "=r"(t) : "f"(x));
    return __uint_as_float(t);
}
__device__ __forceinline__ void mma8(float c[4], const uint32_t a[4], uint32_t b0, uint32_t b1) {
    asm volatile("mma.sync.aligned.m16n8k8.row.col.f32.tf32.tf32.f32 "
                 "{%0,%1,%2,%3},{%4,%5,%6,%7},{%8,%9},{%0,%1,%2,%3};"
                 : "+f"(c[0]), "+f"(c[1]), "+f"(c[2]), "+f"(c[3])
                 : "r"(a[0]), "r"(a[1]), "r"(a[2]), "r"(a[3]), "r"(b0), "r"(b1));
}

// ---------------- pipelined tf32 mainloop ----------------
// CTA tile 128x128, 8 warps in 2(M) x 4(N) grid of 64x32 warp tiles.
// A fragments are used RAW (HMMA reads top-19 bits -> tf32 truncation; for
// gemm2 A=g_H is pre-rounded so this is exact). B fragments get cvt.rna.
template <int NITER>
__device__ __forceinline__ void run_mainloop(
    const float* __restrict__ gA, size_t lda,
    const float* __restrict__ gB, size_t ldb,
    uint32_t sb, int tid, float acc[4][4][4])
{
    const int warpid = tid >> 5, lane = tid & 31;
    const int wm = warpid & 1, wn = warpid >> 1;

    const int rowA = wm * 64 + (lane & 7) + ((lane >> 3) & 1) * 8;
    const int a_hi = (lane >> 4) & 1;
    const int rowB = wn * 32 + (lane & 7) + ((lane >> 4) & 1) * 8;
    const int b_hi = (lane >> 3) & 1;
    const uint32_t baseA = (uint32_t)rowA * 128, swA = rowA & 7;
    const uint32_t baseB = (uint32_t)rowB * 128, swB = rowB & 7;

    auto load_stage = [&](int ki, int slot) {
        uint32_t S  = sb + slot * STAGE_BYTES;
        uint32_t Bs = S + 128 * 128;
        const float* ga = gA + (size_t)ki * BK;
        const float* gb = gB + (size_t)ki * BK;
        #pragma unroll
        for (int j = 0; j < 4; j++) {
            int id = tid + j * 256, row = id >> 3, ch = id & 7;
            cp16(S + row * 128 + ((ch ^ (row & 7)) << 4), ga + (size_t)row * lda + ch * 4);
        }
        #pragma unroll
        for (int j = 0; j < 4; j++) {
            int id = tid + j * 256, row = id >> 3, ch = id & 7;
            cp16(Bs + row * 128 + ((ch ^ (row & 7)) << 4), gb + (size_t)row * ldb + ch * 4);
        }
        CP_COMMIT();
    };

    load_stage(0, 0);
    load_stage(1, 1);

    #pragma unroll 1
    for (int i = 0; i < NITER; i++) {
        if (i + 1 < NITER) cp_wait<1>(); else cp_wait<0>();
        __syncthreads();
        if (i + 2 < NITER) load_stage(i + 2, (i + 2) % NSTAGE);

        uint32_t S   = sb + (i % NSTAGE) * STAGE_BYTES;
        uint32_t Asm = S, Bsm = S + 128 * 128;

        #pragma unroll
        for (int ks = 0; ks < 4; ks++) {           // 4 x k8 per 32-k stage
            uint32_t af[4][4], bf[2][4];
            #pragma unroll
            for (int mi = 0; mi < 4; mi++)
                ldsm4(af[mi], Asm + baseA + mi * 2048 + ((((uint32_t)(ks * 2 + a_hi)) ^ swA) << 4));
            #pragma unroll
            for (int gi = 0; gi < 2; gi++)
                ldsm4(bf[gi], Bsm + baseB + gi * 2048 + ((((uint32_t)(ks * 2 + b_hi)) ^ swB) << 4));
            // A used raw (truncation / pre-rounded). Only B gets cvt.rna.
            #pragma unroll
            for (int gi = 0; gi < 2; gi++)
                #pragma unroll
                for (int q = 0; q < 4; q++) bf[gi][q] = f2tf(bf[gi][q]);
            #pragma unroll
            for (int mi = 0; mi < 4; mi++)
                #pragma unroll
                for (int gi = 0; gi < 2; gi++) {
                    mma8(acc[mi][2 * gi],     af[mi], bf[gi][0], bf[gi][1]);
                    mma8(acc[mi][2 * gi + 1], af[mi], bf[gi][2], bf[gi][3]);
                }
        }
    }
}

// ---------------- GEMM1: g_H[c][b][h] = tf32_rna(relu(x . w1 + b1)) ----------------
__global__ void __launch_bounds__(256, 2) gemm1_mma(
    const float* __restrict__ x, const float* __restrict__ w1, const float* __restrict__ b1)
{
    extern __shared__ char smem[];
    uint32_t sb = (uint32_t)__cvta_generic_to_shared(smem);
    const int tid = threadIdx.x;
    const int nt = blockIdx.x, mt = blockIdx.y, c = blockIdx.z;

    const float* gA = x  + ((size_t)(mt * 128) * C_DIM + c) * I_DIM;   // row stride C*I
    const float* gB = w1 + ((size_t)c * H_DIM + nt * 128) * I_DIM;     // row stride I

    float acc[4][4][4] = {};
    run_mainloop<I_DIM / BK>(gA, (size_t)C_DIM * I_DIM, gB, I_DIM, sb, tid, acc);

    const int warpid = tid >> 5, lane = tid & 31;
    const int wm = warpid & 1, wn = warpid >> 1;
    const int m0 = mt * 128 + wm * 64;
    const int n0 = nt * 128 + wn * 32;
    const float* b1c = b1 + (size_t)c * H_DIM;

    #pragma unroll
    for (int mi = 0; mi < 4; mi++) {
        int r0 = m0 + mi * 16 + (lane >> 2);
        float* h0 = g_H + ((size_t)c * B_DIM + r0) * H_DIM;
        float* h1 = h0 + 8 * H_DIM;
        #pragma unroll
        for (int nj = 0; nj < 4; nj++) {
            int col = n0 + nj * 8 + 2 * (lane & 3);
            float bi0 = b1c[col], bi1 = b1c[col + 1];
            float2 v0, v1;
            v0.x = f2tf_f(fmaxf(acc[mi][nj][0] + bi0, 0.f));
            v0.y = f2tf_f(fmaxf(acc[mi][nj][1] + bi1, 0.f));
            v1.x = f2tf_f(fmaxf(acc[mi][nj][2] + bi0, 0.f));
            v1.y = f2tf_f(fmaxf(acc[mi][nj][3] + bi1, 0.f));
            *(float2*)(h0 + col) = v0;
            *(float2*)(h1 + col) = v1;
        }
    }
}

// ---------------- GEMM2: g_O[c][b][o] = g_H[c][b][:] . w2[c,o,:] + b2[c,o] ----------------
__global__ void __launch_bounds__(256, 2) gemm2_mma(
    const float* __restrict__ w2, const float* __restrict__ b2)
{
    extern __shared__ char smem[];
    uint32_t sb = (uint32_t)__cvta_generic_to_shared(smem);
    const int tid = threadIdx.x;
    const int mt = blockIdx.x, c = blockIdx.y;

    const float* gA = g_H + ((size_t)c * B_DIM + mt * 128) * H_DIM;   // row stride H
    const float* gB = w2  + (size_t)c * O_DIM * H_DIM;                // row stride H

    float acc[4][4][4] = {};
    run_mainloop<H_DIM / BK>(gA, H_DIM, gB, H_DIM, sb, tid, acc);

    const int warpid = tid >> 5, lane = tid & 31;
    const int wm = warpid & 1, wn = warpid >> 1;
    const int m0 = mt * 128 + wm * 64;
    const int n0 = wn * 32;
    const float* b2c = b2 + (size_t)c * O_DIM;

    #pragma unroll
    for (int mi = 0; mi < 4; mi++) {
        int r0 = m0 + mi * 16 + (lane >> 2);
        float* o0 = g_O + ((size_t)c * B_DIM + r0) * O_DIM;
        float* o1 = o0 + 8 * O_DIM;
        #pragma unroll
        for (int nj = 0; nj < 4; nj++) {
            int o = n0 + nj * 8 + 2 * (lane & 3);
            float bi0 = b2c[o], bi1 = b2c[o + 1];
            float2 v0, v1;
            v0.x = acc[mi][nj][0] + bi0;
            v0.y = acc[mi][nj][1] + bi1;
            v1.x = acc[mi][nj][2] + bi0;
            v1.y = acc[mi][nj][3] + bi1;
            *(float2*)(o0 + o) = v0;
            *(float2*)(o1 + o) = v1;
        }
    }
}

// ---------------- transpose: out[b][o][c] = g_O[c][b][o] ----------------
// Treat as 2D transpose of [C=128] x [M=B*O=32768]. 32x32 tiles, both sides coalesced.
__global__ void __launch_bounds__(256) transpose_out(float* __restrict__ out)
{
    __shared__ float s[32][33];
    const int tx = threadIdx.x & 31, ty = threadIdx.x >> 5;   // ty 0..7
    const int m0 = blockIdx.x * 32, c0 = blockIdx.y * 32;
    const int MTOT = B_DIM * O_DIM;

    #pragma unroll
    for (int j = 0; j < 4; j++) {
        int cc = c0 + ty + j * 8;
        s[ty + j * 8][tx] = g_O[(size_t)cc * MTOT + m0 + tx];
    }
    __syncthreads();
    #pragma unroll
    for (int j = 0; j < 4; j++) {
        int m = m0 + ty + j * 8;
        out[(size_t)m * C_DIM + c0 + tx] = s[tx][ty + j * 8];
    }
}

extern "C" void kernel_launch(void* const* d_in, const int* in_sizes, int n_in,
                              void* d_out, int out_size)
{
    const float* x  = (const float*)d_in[0];
    const float* w1 = (const float*)d_in[1];
    const float* b1 = (const float*)d_in[2];
    const float* w2 = (const float*)d_in[3];
    const float* b2 = (const float*)d_in[4];
    float* out = (float*)d_out;

    cudaFuncSetAttribute(gemm1_mma, cudaFuncAttributeMaxDynamicSharedMemorySize, DYN_SMEM);
    cudaFuncSetAttribute(gemm2_mma, cudaFuncAttributeMaxDynamicSharedMemorySize, DYN_SMEM);

    dim3 g1(H_DIM / 128, B_DIM / 128, C_DIM);   // (8, 2, 128)
    gemm1_mma<<<g1, 256, DYN_SMEM>>>(x, w1, b1);

    dim3 g2(B_DIM / 128, C_DIM);                // (2, 128)
    gemm2_mma<<<g2, 256, DYN_SMEM>>>(w2, b2);

    dim3 gt((B_DIM * O_DIM) / 32, C_DIM / 32);  // (1024, 4)
    transpose_out<<<gt, 256>>>(out);
}